// round 15
// baseline (speedup 1.0000x reference)
#include <cuda_runtime.h>
#include <cuda_fp16.h>
#include <math.h>

// Problem constants
#define BATCH    64
#define IN_CAPS  2048
#define IN_DIM   8
#define NC       32
#define OUT_DIM  16
#define NV       (BATCH * NC * OUT_DIM)  // 32768

// pass A tiling (W-heavy): 2 rows/thread for W reuse
#define IBLK_A   32
#define NIB_A    (IN_CAPS / IBLK_A)      // 64
#define BTILE    8                       // 4 warps x 2 rows
#define NBT      (BATCH / BTILE)         // 8
// pass B/C tiling (stream-light)
#define IBLK_B   16
#define NIB_B    (IN_CAPS / IBLK_B)      // 128

typedef unsigned long long u64t;

// Scratch (static device globals — no allocation allowed)
__device__ __align__(16) float  g_s[3][NV];
__device__ __align__(16) __half g_u[(size_t)BATCH * IN_CAPS * NC * OUT_DIM]; // 134MB
// Transposed weights: W_t[i][d][e/4][n] as float4  (32MB, L2-resident)
__device__ __align__(16) float4 g_Wt4[(size_t)IN_CAPS * IN_DIM * 4 * NC];

// ---- packed f32x2 helpers (Blackwell FFMA2, PTX-only) ----
__device__ __forceinline__ u64t pk2(float lo, float hi) {
    u64t r; asm("mov.b64 %0,{%1,%2};" : "=l"(r) : "f"(lo), "f"(hi)); return r;
}
__device__ __forceinline__ void upk2(u64t v, float& lo, float& hi) {
    asm("mov.b64 {%0,%1},%2;" : "=f"(lo), "=f"(hi) : "l"(v));
}
__device__ __forceinline__ u64t fma2(u64t a, u64t b, u64t c) {
    u64t d; asm("fma.rn.f32x2 %0,%1,%2,%3;" : "=l"(d) : "l"(a), "l"(b), "l"(c)); return d;
}
__device__ __forceinline__ u64t add2(u64t a, u64t b) {
    u64t d; asm("add.rn.f32x2 %0,%1,%2;" : "=l"(d) : "l"(a), "l"(b)); return d;
}
// packed fire-and-forget global reduction
__device__ __forceinline__ void red_add_v2(float* addr, float a, float b) {
    asm volatile("red.global.add.v2.f32 [%0], {%1,%2};" :: "l"(addr), "f"(a), "f"(b) : "memory");
}
// streaming (evict-first) 16B load/store
__device__ __forceinline__ uint4 ldcs16(const uint4* p) {
    uint4 v;
    asm volatile("ld.global.cs.v4.u32 {%0,%1,%2,%3},[%4];"
                 : "=r"(v.x), "=r"(v.y), "=r"(v.z), "=r"(v.w) : "l"(p));
    return v;
}
__device__ __forceinline__ void stcs16(uint4* p, uint4 v) {
    asm volatile("st.global.cs.v4.u32 [%0],{%1,%2,%3,%4};"
                 :: "l"(p), "r"(v.x), "r"(v.y), "r"(v.z), "r"(v.w) : "memory");
}
// f32x2 (u64) -> half2 word
__device__ __forceinline__ unsigned h2_from_f2(u64t f2) {
    float lo, hi; upk2(f2, lo, hi);
    __half2 h = __floats2half2_rn(lo, hi);
    return *(unsigned*)&h;
}
// half2 word -> f32x2 (u64)
__device__ __forceinline__ u64t f2_from_h2(unsigned w) {
    __half2 h = *(__half2*)&w;
    float2 f = __half22float2(h);
    return pk2(f.x, f.y);
}

// W[i][n][d][e] (row-major) -> W_t[i][d*4+q][n] float4 (q = e/4)
// Also zero-initializes the g_s accumulators.
__global__ void __launch_bounds__(256)
transpose_W(const float4* __restrict__ W4) {
    __shared__ float4 t[32][33];
    const int i   = blockIdx.x;
    const int tid = threadIdx.x;
    if (i < 48) {
        int base = (i * 256 + tid) * 8;
#pragma unroll
        for (int k = 0; k < 8; k++)
            if (base + k < 3 * NV) ((float*)g_s)[base + k] = 0.0f;
    }
    const float4* src = W4 + (size_t)i * 1024;
#pragma unroll
    for (int k = 0; k < 4; k++) {
        int idx = tid + 256 * k;
        t[idx >> 5][idx & 31] = src[idx];
    }
    __syncthreads();
    float4* dst = g_Wt4 + (size_t)i * 1024;
#pragma unroll
    for (int k = 0; k < 4; k++) {
        int idx = tid + 256 * k;
        dst[idx] = t[idx & 31][idx >> 5];
    }
}

// inline squash of one 16-vector from g_s[K] (scale applied before squash)
__device__ __forceinline__ void squash_row(const float* sp, float scale, float* w) {
    const float4* s4 = (const float4*)sp;
    float4 r0 = s4[0], r1 = s4[1], r2 = s4[2], r3 = s4[3];
    w[0]=r0.x*scale; w[1]=r0.y*scale; w[2]=r0.z*scale; w[3]=r0.w*scale;
    w[4]=r1.x*scale; w[5]=r1.y*scale; w[6]=r1.z*scale; w[7]=r1.w*scale;
    w[8]=r2.x*scale; w[9]=r2.y*scale; w[10]=r2.z*scale; w[11]=r2.w*scale;
    w[12]=r3.x*scale; w[13]=r3.y*scale; w[14]=r3.z*scale; w[15]=r3.w*scale;
    float s2 = 0.0f;
#pragma unroll
    for (int e = 0; e < OUT_DIM; e++) s2 += w[e] * w[e];
    float sc = s2 / ((1.0f + s2) * sqrtf(fmaxf(s2, 1e-30f)));
#pragma unroll
    for (int e = 0; e < OUT_DIM; e++) w[e] *= sc;
}

// ===== Pass A: u_hat = x.W once; store fp16 (streaming); s0 = sum_i u =====
__global__ void __launch_bounds__(128, 4)
passA_kernel(const float* __restrict__ x) {
    const int tid = threadIdx.x;
    const int n   = tid & 31;
    const int g   = tid >> 5;
    const int bA  = blockIdx.y * BTILE + g * 2;
    const int bB  = bA + 1;
    const int i0  = blockIdx.x * IBLK_A;

    u64t accA2[8], accB2[8];
#pragma unroll
    for (int q = 0; q < 8; q++) { accA2[q] = 0ull; accB2[q] = 0ull; }

    for (int ii = 0; ii < IBLK_A; ii++) {
        const int i = i0 + ii;
        const float4* xrA = (const float4*)(x + ((size_t)bA * IN_CAPS + i) * IN_DIM);
        const float4* xrB = (const float4*)(x + ((size_t)bB * IN_CAPS + i) * IN_DIM);
        float4 xa0 = __ldg(xrA), xa1 = __ldg(xrA + 1);
        float4 xb0 = __ldg(xrB), xb1 = __ldg(xrB + 1);
        float xsA[8] = {xa0.x, xa0.y, xa0.z, xa0.w, xa1.x, xa1.y, xa1.z, xa1.w};
        float xsB[8] = {xb0.x, xb0.y, xb0.z, xb0.w, xb1.x, xb1.y, xb1.z, xb1.w};

        const float4* wp = g_Wt4 + (size_t)i * 1024 + n;

        u64t uA2[8], uB2[8];
#pragma unroll
        for (int q = 0; q < 8; q++) { uA2[q] = 0ull; uB2[q] = 0ull; }
#pragma unroll
        for (int d = 0; d < IN_DIM; d++) {
            u64t xa2 = pk2(xsA[d], xsA[d]);
            u64t xb2 = pk2(xsB[d], xsB[d]);
#pragma unroll
            for (int q = 0; q < 4; q++) {
                float4 w = __ldg(wp + (d * 4 + q) * 32);
                u64t w01 = pk2(w.x, w.y), w23 = pk2(w.z, w.w);
                uA2[2 * q]     = fma2(w01, xa2, uA2[2 * q]);
                uA2[2 * q + 1] = fma2(w23, xa2, uA2[2 * q + 1]);
                uB2[2 * q]     = fma2(w01, xb2, uB2[2 * q]);
                uB2[2 * q + 1] = fma2(w23, xb2, uB2[2 * q + 1]);
            }
        }
#pragma unroll
        for (int q = 0; q < 8; q++) {
            accA2[q] = add2(accA2[q], uA2[q]);
            accB2[q] = add2(accB2[q], uB2[q]);
        }
        uint4 pa0, pa1, pb0, pb1;
        pa0.x = h2_from_f2(uA2[0]); pa0.y = h2_from_f2(uA2[1]);
        pa0.z = h2_from_f2(uA2[2]); pa0.w = h2_from_f2(uA2[3]);
        pa1.x = h2_from_f2(uA2[4]); pa1.y = h2_from_f2(uA2[5]);
        pa1.z = h2_from_f2(uA2[6]); pa1.w = h2_from_f2(uA2[7]);
        pb0.x = h2_from_f2(uB2[0]); pb0.y = h2_from_f2(uB2[1]);
        pb0.z = h2_from_f2(uB2[2]); pb0.w = h2_from_f2(uB2[3]);
        pb1.x = h2_from_f2(uB2[4]); pb1.y = h2_from_f2(uB2[5]);
        pb1.z = h2_from_f2(uB2[6]); pb1.w = h2_from_f2(uB2[7]);
        uint4* uoutA = (uint4*)g_u + (((size_t)bA * IN_CAPS + i) * NC + n) * 2;
        uint4* uoutB = (uint4*)g_u + (((size_t)bB * IN_CAPS + i) * NC + n) * 2;
        stcs16(uoutA, pa0); stcs16(uoutA + 1, pa1);
        stcs16(uoutB, pb0); stcs16(uoutB + 1, pb1);
    }

    float* s = g_s[0];
#pragma unroll
    for (int q = 0; q < 8; q++) {
        float a0, a1, b0, b1;
        upk2(accA2[q], a0, a1); upk2(accB2[q], b0, b1);
        red_add_v2(&s[(bA * NC + n) * OUT_DIM + 2 * q], a0, a1);
        red_add_v2(&s[(bB * NC + n) * OUT_DIM + 2 * q], b0, b1);
    }
}

// ===== Pass B/C (P=1,2): stream u fp16 (2 capsules/iter = 4 chains in flight)
// P=1: logit = u.v0.       P=2: logit = u.(v0+v1)  [exact: b2 = u.v0 + u.v1]
// No logits buffer needed at all. u kept as half2 registers (low pressure).
template <int P>
__global__ void __launch_bounds__(128, 5)
route_kernel() {
    __shared__ u64t vs[4][2][8][32];   // w[warp][row][q][n]  (w = v0 or v0+v1)

    const int tid = threadIdx.x;
    const int n   = tid & 31;
    const int g   = tid >> 5;
    const int bA  = blockIdx.y * BTILE + g * 2;
    const int bB  = bA + 1;
    const int i0  = blockIdx.x * IBLK_B;

    u64t accA2[8], accB2[8];
#pragma unroll
    for (int q = 0; q < 8; q++) { accA2[q] = 0ull; accB2[q] = 0ull; }

    {
        float wA[OUT_DIM], wB[OUT_DIM];
        squash_row(&g_s[0][(bA * NC + n) * OUT_DIM], 1.0f / 32.0f, wA);   // v0
        squash_row(&g_s[0][(bB * NC + n) * OUT_DIM], 1.0f / 32.0f, wB);
        if constexpr (P == 2) {
            float tA[OUT_DIM], tB[OUT_DIM];
            squash_row(&g_s[1][(bA * NC + n) * OUT_DIM], 1.0f, tA);       // v1
            squash_row(&g_s[1][(bB * NC + n) * OUT_DIM], 1.0f, tB);
#pragma unroll
            for (int e = 0; e < OUT_DIM; e++) { wA[e] += tA[e]; wB[e] += tB[e]; }
        }
#pragma unroll
        for (int q = 0; q < 8; q++) {
            vs[g][0][q][n] = pk2(wA[2 * q], wA[2 * q + 1]);
            vs[g][1][q][n] = pk2(wB[2 * q], wB[2 * q + 1]);
        }
        __syncwarp();   // each warp only reads its own slice
    }

    for (int ii = 0; ii < IBLK_B; ii += 2) {
        const int ia = i0 + ii, ib = i0 + ii + 1;

        const uint4* pAa = (const uint4*)g_u + (((size_t)bA * IN_CAPS + ia) * NC + n) * 2;
        const uint4* pBa = (const uint4*)g_u + (((size_t)bB * IN_CAPS + ia) * NC + n) * 2;
        const uint4* pAb = (const uint4*)g_u + (((size_t)bA * IN_CAPS + ib) * NC + n) * 2;
        const uint4* pBb = (const uint4*)g_u + (((size_t)bB * IN_CAPS + ib) * NC + n) * 2;
        uint4 hAa0 = ldcs16(pAa), hAa1 = ldcs16(pAa + 1);
        uint4 hBa0 = ldcs16(pBa), hBa1 = ldcs16(pBa + 1);
        uint4 hAb0 = ldcs16(pAb), hAb1 = ldcs16(pAb + 1);
        uint4 hBb0 = ldcs16(pBb), hBb1 = ldcs16(pBb + 1);

        // u stays as half2 words (half the registers of f32x2)
        unsigned uAa[8] = {hAa0.x, hAa0.y, hAa0.z, hAa0.w, hAa1.x, hAa1.y, hAa1.z, hAa1.w};
        unsigned uBa[8] = {hBa0.x, hBa0.y, hBa0.z, hBa0.w, hBa1.x, hBa1.y, hBa1.z, hBa1.w};
        unsigned uAb[8] = {hAb0.x, hAb0.y, hAb0.z, hAb0.w, hAb1.x, hAb1.y, hAb1.z, hAb1.w};
        unsigned uBb[8] = {hBb0.x, hBb0.y, hBb0.z, hBb0.w, hBb1.x, hBb1.y, hBb1.z, hBb1.w};

        // 4 dot products, 2 chains each (convert half2 -> f32x2 on the fly)
        u64t dAa0=0, dAa1=0, dBa0=0, dBa1=0, dAb0=0, dAb1=0, dBb0=0, dBb1=0;
#pragma unroll
        for (int q = 0; q < 8; q += 2) {
            u64t v0A = vs[g][0][q][n], v1A = vs[g][0][q + 1][n];
            u64t v0B = vs[g][1][q][n], v1B = vs[g][1][q + 1][n];
            dAa0 = fma2(f2_from_h2(uAa[q]),     v0A, dAa0);
            dAa1 = fma2(f2_from_h2(uAa[q + 1]), v1A, dAa1);
            dBa0 = fma2(f2_from_h2(uBa[q]),     v0B, dBa0);
            dBa1 = fma2(f2_from_h2(uBa[q + 1]), v1B, dBa1);
            dAb0 = fma2(f2_from_h2(uAb[q]),     v0A, dAb0);
            dAb1 = fma2(f2_from_h2(uAb[q + 1]), v1A, dAb1);
            dBb0 = fma2(f2_from_h2(uBb[q]),     v0B, dBb0);
            dBb1 = fma2(f2_from_h2(uBb[q + 1]), v1B, dBb1);
        }
        float t0, t1;
        upk2(add2(dAa0, dAa1), t0, t1); float lAa = t0 + t1;
        upk2(add2(dBa0, dBa1), t0, t1); float lBa = t0 + t1;
        upk2(add2(dAb0, dAb1), t0, t1); float lAb = t0 + t1;
        upk2(add2(dBb0, dBb1), t0, t1); float lBb = t0 + t1;

        // softmax over 32 capsules (no max subtraction: logits bounded << 88)
        float eAa = __expf(lAa), eBa = __expf(lBa);
        float eAb = __expf(lAb), eBb = __expf(lBb);
        float ZAa = eAa, ZBa = eBa, ZAb = eAb, ZBb = eBb;
#pragma unroll
        for (int o = 16; o > 0; o >>= 1) {     // 4 trees interleave
            ZAa += __shfl_xor_sync(0xffffffffu, ZAa, o);
            ZBa += __shfl_xor_sync(0xffffffffu, ZBa, o);
            ZAb += __shfl_xor_sync(0xffffffffu, ZAb, o);
            ZBb += __shfl_xor_sync(0xffffffffu, ZBb, o);
        }
        float cAa = __fdividef(eAa, ZAa), cBa = __fdividef(eBa, ZBa);
        float cAb = __fdividef(eAb, ZAb), cBb = __fdividef(eBb, ZBb);
        u64t cAa2 = pk2(cAa, cAa), cBa2 = pk2(cBa, cBa);
        u64t cAb2 = pk2(cAb, cAb), cBb2 = pk2(cBb, cBb);
#pragma unroll
        for (int q = 0; q < 8; q++) {
            accA2[q] = fma2(f2_from_h2(uAa[q]), cAa2, accA2[q]);
            accB2[q] = fma2(f2_from_h2(uBa[q]), cBa2, accB2[q]);
            accA2[q] = fma2(f2_from_h2(uAb[q]), cAb2, accA2[q]);
            accB2[q] = fma2(f2_from_h2(uBb[q]), cBb2, accB2[q]);
        }
    }

    float* s = g_s[P];
#pragma unroll
    for (int q = 0; q < 8; q++) {
        float a0, a1, b0, b1;
        upk2(accA2[q], a0, a1); upk2(accB2[q], b0, b1);
        red_add_v2(&s[(bA * NC + n) * OUT_DIM + 2 * q], a0, a1);
        red_add_v2(&s[(bB * NC + n) * OUT_DIM + 2 * q], b0, b1);
    }
}

// final squash of g_s[2] -> output
__global__ void squash_out_kernel(float* out) {
    int idx = blockIdx.x * blockDim.x + threadIdx.x;
    if (idx >= BATCH * NC) return;
    float w[OUT_DIM];
    squash_row(&g_s[2][idx * OUT_DIM], 1.0f, w);
#pragma unroll
    for (int e = 0; e < OUT_DIM; e++) out[idx * OUT_DIM + e] = w[e];
}

extern "C" void kernel_launch(void* const* d_in, const int* in_sizes, int n_in,
                              void* d_out, int out_size) {
    const float* x = (const float*)d_in[0];   // [64, 2048, 8]
    const float* W = (const float*)d_in[1];   // [2048, 32, 8, 16]
    float* out = (float*)d_out;               // [64, 32, 16]

    transpose_W<<<IN_CAPS, 256>>>((const float4*)W);   // also zeroes g_s

    dim3 gridA(NIB_A, NBT);                   // 64 x 8  = 512 CTAs
    dim3 gridB(NIB_B, NBT);                   // 128 x 8 = 1024 CTAs
    dim3 sgrid((BATCH * NC + 255) / 256);

    passA_kernel<<<gridA, 128>>>(x);
    route_kernel<1><<<gridB, 128>>>();        // logit = u.v0      (squash inline)
    route_kernel<2><<<gridB, 128>>>();        // logit = u.(v0+v1) (squash inline)
    squash_out_kernel<<<sgrid, 256>>>(out);
}

// round 16
// speedup vs baseline: 1.0362x; 1.0362x over previous
#include <cuda_runtime.h>
#include <cuda_fp16.h>
#include <math.h>

// Problem constants
#define BATCH    64
#define IN_CAPS  2048
#define IN_DIM   8
#define NC       32
#define OUT_DIM  16
#define NV       (BATCH * NC * OUT_DIM)  // 32768

// pass A tiling (W-heavy): 2 rows/thread for W reuse
#define IBLK_A   32
#define NIB_A    (IN_CAPS / IBLK_A)      // 64
#define BTILE    8                       // 4 warps x 2 rows
#define NBT      (BATCH / BTILE)         // 8
// pass B/C tiling (stream-light)
#define IBLK_B   16
#define NIB_B    (IN_CAPS / IBLK_B)      // 128

typedef unsigned long long u64t;

// Scratch (static device globals — no allocation allowed)
__device__ __align__(16) float  g_s[3][NV];
__device__ __align__(16) __half g_u[(size_t)BATCH * IN_CAPS * NC * OUT_DIM]; // 134MB
// Transposed weights: W_t[i][d][e/4][n] as float4  (32MB, L2-resident)
__device__ __align__(16) float4 g_Wt4[(size_t)IN_CAPS * IN_DIM * 4 * NC];

// ---- packed f32x2 helpers (Blackwell FFMA2, PTX-only) ----
__device__ __forceinline__ u64t pk2(float lo, float hi) {
    u64t r; asm("mov.b64 %0,{%1,%2};" : "=l"(r) : "f"(lo), "f"(hi)); return r;
}
__device__ __forceinline__ void upk2(u64t v, float& lo, float& hi) {
    asm("mov.b64 {%0,%1},%2;" : "=f"(lo), "=f"(hi) : "l"(v));
}
__device__ __forceinline__ u64t fma2(u64t a, u64t b, u64t c) {
    u64t d; asm("fma.rn.f32x2 %0,%1,%2,%3;" : "=l"(d) : "l"(a), "l"(b), "l"(c)); return d;
}
__device__ __forceinline__ u64t add2(u64t a, u64t b) {
    u64t d; asm("add.rn.f32x2 %0,%1,%2;" : "=l"(d) : "l"(a), "l"(b)); return d;
}
// packed fire-and-forget global reduction
__device__ __forceinline__ void red_add_v2(float* addr, float a, float b) {
    asm volatile("red.global.add.v2.f32 [%0], {%1,%2};" :: "l"(addr), "f"(a), "f"(b) : "memory");
}
// streaming (evict-first) 16B load/store
__device__ __forceinline__ uint4 ldcs16(const uint4* p) {
    uint4 v;
    asm volatile("ld.global.cs.v4.u32 {%0,%1,%2,%3},[%4];"
                 : "=r"(v.x), "=r"(v.y), "=r"(v.z), "=r"(v.w) : "l"(p));
    return v;
}
__device__ __forceinline__ void stcs16(uint4* p, uint4 v) {
    asm volatile("st.global.cs.v4.u32 [%0],{%1,%2,%3,%4};"
                 :: "l"(p), "r"(v.x), "r"(v.y), "r"(v.z), "r"(v.w) : "memory");
}
// f32x2 (u64) -> half2 word
__device__ __forceinline__ unsigned h2_from_f2(u64t f2) {
    float lo, hi; upk2(f2, lo, hi);
    __half2 h = __floats2half2_rn(lo, hi);
    return *(unsigned*)&h;
}
// half2 word -> f32x2 (u64)
__device__ __forceinline__ u64t f2_from_h2(unsigned w) {
    __half2 h = *(__half2*)&w;
    float2 f = __half22float2(h);
    return pk2(f.x, f.y);
}

// W[i][n][d][e] (row-major) -> W_t[i][d*4+q][n] float4 (q = e/4)
// Also zero-initializes the g_s accumulators.
__global__ void __launch_bounds__(256)
transpose_W(const float4* __restrict__ W4) {
    __shared__ float4 t[32][33];
    const int i   = blockIdx.x;
    const int tid = threadIdx.x;
    if (i < 48) {
        int base = (i * 256 + tid) * 8;
#pragma unroll
        for (int k = 0; k < 8; k++)
            if (base + k < 3 * NV) ((float*)g_s)[base + k] = 0.0f;
    }
    const float4* src = W4 + (size_t)i * 1024;
#pragma unroll
    for (int k = 0; k < 4; k++) {
        int idx = tid + 256 * k;
        t[idx >> 5][idx & 31] = src[idx];
    }
    __syncthreads();
    float4* dst = g_Wt4 + (size_t)i * 1024;
#pragma unroll
    for (int k = 0; k < 4; k++) {
        int idx = tid + 256 * k;
        dst[idx] = t[idx & 31][idx >> 5];
    }
}

// inline squash of one 16-vector from g_s[K] (scale applied before squash)
__device__ __forceinline__ void squash_row(const float* sp, float scale, float* w) {
    const float4* s4 = (const float4*)sp;
    float4 r0 = s4[0], r1 = s4[1], r2 = s4[2], r3 = s4[3];
    w[0]=r0.x*scale; w[1]=r0.y*scale; w[2]=r0.z*scale; w[3]=r0.w*scale;
    w[4]=r1.x*scale; w[5]=r1.y*scale; w[6]=r1.z*scale; w[7]=r1.w*scale;
    w[8]=r2.x*scale; w[9]=r2.y*scale; w[10]=r2.z*scale; w[11]=r2.w*scale;
    w[12]=r3.x*scale; w[13]=r3.y*scale; w[14]=r3.z*scale; w[15]=r3.w*scale;
    float s2 = 0.0f;
#pragma unroll
    for (int e = 0; e < OUT_DIM; e++) s2 += w[e] * w[e];
    float sc = s2 / ((1.0f + s2) * sqrtf(fmaxf(s2, 1e-30f)));
#pragma unroll
    for (int e = 0; e < OUT_DIM; e++) w[e] *= sc;
}

// ===== Pass A: u_hat = x.W once; store fp16 (streaming); s0 = sum_i u =====
__global__ void __launch_bounds__(128, 4)
passA_kernel(const float* __restrict__ x) {
    const int tid = threadIdx.x;
    const int n   = tid & 31;
    const int g   = tid >> 5;
    const int bA  = blockIdx.y * BTILE + g * 2;
    const int bB  = bA + 1;
    const int i0  = blockIdx.x * IBLK_A;

    u64t accA2[8], accB2[8];
#pragma unroll
    for (int q = 0; q < 8; q++) { accA2[q] = 0ull; accB2[q] = 0ull; }

    for (int ii = 0; ii < IBLK_A; ii++) {
        const int i = i0 + ii;
        const float4* xrA = (const float4*)(x + ((size_t)bA * IN_CAPS + i) * IN_DIM);
        const float4* xrB = (const float4*)(x + ((size_t)bB * IN_CAPS + i) * IN_DIM);
        float4 xa0 = __ldg(xrA), xa1 = __ldg(xrA + 1);
        float4 xb0 = __ldg(xrB), xb1 = __ldg(xrB + 1);
        float xsA[8] = {xa0.x, xa0.y, xa0.z, xa0.w, xa1.x, xa1.y, xa1.z, xa1.w};
        float xsB[8] = {xb0.x, xb0.y, xb0.z, xb0.w, xb1.x, xb1.y, xb1.z, xb1.w};

        const float4* wp = g_Wt4 + (size_t)i * 1024 + n;

        u64t uA2[8], uB2[8];
#pragma unroll
        for (int q = 0; q < 8; q++) { uA2[q] = 0ull; uB2[q] = 0ull; }
#pragma unroll
        for (int d = 0; d < IN_DIM; d++) {
            u64t xa2 = pk2(xsA[d], xsA[d]);
            u64t xb2 = pk2(xsB[d], xsB[d]);
#pragma unroll
            for (int q = 0; q < 4; q++) {
                float4 w = __ldg(wp + (d * 4 + q) * 32);
                u64t w01 = pk2(w.x, w.y), w23 = pk2(w.z, w.w);
                uA2[2 * q]     = fma2(w01, xa2, uA2[2 * q]);
                uA2[2 * q + 1] = fma2(w23, xa2, uA2[2 * q + 1]);
                uB2[2 * q]     = fma2(w01, xb2, uB2[2 * q]);
                uB2[2 * q + 1] = fma2(w23, xb2, uB2[2 * q + 1]);
            }
        }
#pragma unroll
        for (int q = 0; q < 8; q++) {
            accA2[q] = add2(accA2[q], uA2[q]);
            accB2[q] = add2(accB2[q], uB2[q]);
        }
        uint4 pa0, pa1, pb0, pb1;
        pa0.x = h2_from_f2(uA2[0]); pa0.y = h2_from_f2(uA2[1]);
        pa0.z = h2_from_f2(uA2[2]); pa0.w = h2_from_f2(uA2[3]);
        pa1.x = h2_from_f2(uA2[4]); pa1.y = h2_from_f2(uA2[5]);
        pa1.z = h2_from_f2(uA2[6]); pa1.w = h2_from_f2(uA2[7]);
        pb0.x = h2_from_f2(uB2[0]); pb0.y = h2_from_f2(uB2[1]);
        pb0.z = h2_from_f2(uB2[2]); pb0.w = h2_from_f2(uB2[3]);
        pb1.x = h2_from_f2(uB2[4]); pb1.y = h2_from_f2(uB2[5]);
        pb1.z = h2_from_f2(uB2[6]); pb1.w = h2_from_f2(uB2[7]);
        uint4* uoutA = (uint4*)g_u + (((size_t)bA * IN_CAPS + i) * NC + n) * 2;
        uint4* uoutB = (uint4*)g_u + (((size_t)bB * IN_CAPS + i) * NC + n) * 2;
        stcs16(uoutA, pa0); stcs16(uoutA + 1, pa1);
        stcs16(uoutB, pb0); stcs16(uoutB + 1, pb1);
    }

    float* s = g_s[0];
#pragma unroll
    for (int q = 0; q < 8; q++) {
        float a0, a1, b0, b1;
        upk2(accA2[q], a0, a1); upk2(accB2[q], b0, b1);
        red_add_v2(&s[(bA * NC + n) * OUT_DIM + 2 * q], a0, a1);
        red_add_v2(&s[(bB * NC + n) * OUT_DIM + 2 * q], b0, b1);
    }
}

// ===== Pass B/C (P=1,2): stream u fp16 (2 capsules/iter = 4 chains in flight)
// P=1: logit = u.v0.   P=2: logit = u.(v0+v1)  [exact: b2 = u.v0 + u.v1]
// No logits buffer. u converted to f32x2 ONCE after load (R13-proven body). =====
template <int P>
__global__ void __launch_bounds__(128, 4)
route_kernel() {
    __shared__ u64t vs[4][2][8][32];   // w[warp][row][q][n]  (w = v0 or v0+v1)

    const int tid = threadIdx.x;
    const int n   = tid & 31;
    const int g   = tid >> 5;
    const int bA  = blockIdx.y * BTILE + g * 2;
    const int bB  = bA + 1;
    const int i0  = blockIdx.x * IBLK_B;

    u64t accA2[8], accB2[8];
#pragma unroll
    for (int q = 0; q < 8; q++) { accA2[q] = 0ull; accB2[q] = 0ull; }

    {
        float wA[OUT_DIM], wB[OUT_DIM];
        squash_row(&g_s[0][(bA * NC + n) * OUT_DIM], 1.0f / 32.0f, wA);   // v0
        squash_row(&g_s[0][(bB * NC + n) * OUT_DIM], 1.0f / 32.0f, wB);
        if constexpr (P == 2) {
            float tA[OUT_DIM], tB[OUT_DIM];
            squash_row(&g_s[1][(bA * NC + n) * OUT_DIM], 1.0f, tA);       // v1
            squash_row(&g_s[1][(bB * NC + n) * OUT_DIM], 1.0f, tB);
#pragma unroll
            for (int e = 0; e < OUT_DIM; e++) { wA[e] += tA[e]; wB[e] += tB[e]; }
        }
#pragma unroll
        for (int q = 0; q < 8; q++) {
            vs[g][0][q][n] = pk2(wA[2 * q], wA[2 * q + 1]);
            vs[g][1][q][n] = pk2(wB[2 * q], wB[2 * q + 1]);
        }
        __syncwarp();   // each warp only reads its own slice
    }

    for (int ii = 0; ii < IBLK_B; ii += 2) {
        const int ia = i0 + ii, ib = i0 + ii + 1;

        const uint4* pAa = (const uint4*)g_u + (((size_t)bA * IN_CAPS + ia) * NC + n) * 2;
        const uint4* pBa = (const uint4*)g_u + (((size_t)bB * IN_CAPS + ia) * NC + n) * 2;
        const uint4* pAb = (const uint4*)g_u + (((size_t)bA * IN_CAPS + ib) * NC + n) * 2;
        const uint4* pBb = (const uint4*)g_u + (((size_t)bB * IN_CAPS + ib) * NC + n) * 2;
        uint4 hAa0 = ldcs16(pAa), hAa1 = ldcs16(pAa + 1);
        uint4 hBa0 = ldcs16(pBa), hBa1 = ldcs16(pBa + 1);
        uint4 hAb0 = ldcs16(pAb), hAb1 = ldcs16(pAb + 1);
        uint4 hBb0 = ldcs16(pBb), hBb1 = ldcs16(pBb + 1);

        // convert once to f32x2 registers (R13-proven: keeps FMA chains clean)
        u64t uAa[8], uBa[8], uAb[8], uBb[8];
        uAa[0]=f2_from_h2(hAa0.x); uAa[1]=f2_from_h2(hAa0.y); uAa[2]=f2_from_h2(hAa0.z); uAa[3]=f2_from_h2(hAa0.w);
        uAa[4]=f2_from_h2(hAa1.x); uAa[5]=f2_from_h2(hAa1.y); uAa[6]=f2_from_h2(hAa1.z); uAa[7]=f2_from_h2(hAa1.w);
        uBa[0]=f2_from_h2(hBa0.x); uBa[1]=f2_from_h2(hBa0.y); uBa[2]=f2_from_h2(hBa0.z); uBa[3]=f2_from_h2(hBa0.w);
        uBa[4]=f2_from_h2(hBa1.x); uBa[5]=f2_from_h2(hBa1.y); uBa[6]=f2_from_h2(hBa1.z); uBa[7]=f2_from_h2(hBa1.w);
        uAb[0]=f2_from_h2(hAb0.x); uAb[1]=f2_from_h2(hAb0.y); uAb[2]=f2_from_h2(hAb0.z); uAb[3]=f2_from_h2(hAb0.w);
        uAb[4]=f2_from_h2(hAb1.x); uAb[5]=f2_from_h2(hAb1.y); uAb[6]=f2_from_h2(hAb1.z); uAb[7]=f2_from_h2(hAb1.w);
        uBb[0]=f2_from_h2(hBb0.x); uBb[1]=f2_from_h2(hBb0.y); uBb[2]=f2_from_h2(hBb0.z); uBb[3]=f2_from_h2(hBb0.w);
        uBb[4]=f2_from_h2(hBb1.x); uBb[5]=f2_from_h2(hBb1.y); uBb[6]=f2_from_h2(hBb1.z); uBb[7]=f2_from_h2(hBb1.w);

        // 4 dot products, 2 chains each
        u64t dAa0=0, dAa1=0, dBa0=0, dBa1=0, dAb0=0, dAb1=0, dBb0=0, dBb1=0;
#pragma unroll
        for (int q = 0; q < 8; q += 2) {
            u64t v0A = vs[g][0][q][n], v1A = vs[g][0][q + 1][n];
            u64t v0B = vs[g][1][q][n], v1B = vs[g][1][q + 1][n];
            dAa0 = fma2(uAa[q], v0A, dAa0); dAa1 = fma2(uAa[q + 1], v1A, dAa1);
            dBa0 = fma2(uBa[q], v0B, dBa0); dBa1 = fma2(uBa[q + 1], v1B, dBa1);
            dAb0 = fma2(uAb[q], v0A, dAb0); dAb1 = fma2(uAb[q + 1], v1A, dAb1);
            dBb0 = fma2(uBb[q], v0B, dBb0); dBb1 = fma2(uBb[q + 1], v1B, dBb1);
        }
        float t0, t1;
        upk2(add2(dAa0, dAa1), t0, t1); float lAa = t0 + t1;
        upk2(add2(dBa0, dBa1), t0, t1); float lBa = t0 + t1;
        upk2(add2(dAb0, dAb1), t0, t1); float lAb = t0 + t1;
        upk2(add2(dBb0, dBb1), t0, t1); float lBb = t0 + t1;

        // softmax over 32 capsules (no max subtraction: logits bounded << 88)
        float eAa = __expf(lAa), eBa = __expf(lBa);
        float eAb = __expf(lAb), eBb = __expf(lBb);
        float ZAa = eAa, ZBa = eBa, ZAb = eAb, ZBb = eBb;
#pragma unroll
        for (int o = 16; o > 0; o >>= 1) {     // 4 trees interleave
            ZAa += __shfl_xor_sync(0xffffffffu, ZAa, o);
            ZBa += __shfl_xor_sync(0xffffffffu, ZBa, o);
            ZAb += __shfl_xor_sync(0xffffffffu, ZAb, o);
            ZBb += __shfl_xor_sync(0xffffffffu, ZBb, o);
        }
        float cAa = __fdividef(eAa, ZAa), cBa = __fdividef(eBa, ZBa);
        float cAb = __fdividef(eAb, ZAb), cBb = __fdividef(eBb, ZBb);
        u64t cAa2 = pk2(cAa, cAa), cBa2 = pk2(cBa, cBa);
        u64t cAb2 = pk2(cAb, cAb), cBb2 = pk2(cBb, cBb);
#pragma unroll
        for (int q = 0; q < 8; q++) {
            accA2[q] = fma2(uAa[q], cAa2, accA2[q]);
            accB2[q] = fma2(uBa[q], cBa2, accB2[q]);
            accA2[q] = fma2(uAb[q], cAb2, accA2[q]);
            accB2[q] = fma2(uBb[q], cBb2, accB2[q]);
        }
    }

    float* s = g_s[P];
#pragma unroll
    for (int q = 0; q < 8; q++) {
        float a0, a1, b0, b1;
        upk2(accA2[q], a0, a1); upk2(accB2[q], b0, b1);
        red_add_v2(&s[(bA * NC + n) * OUT_DIM + 2 * q], a0, a1);
        red_add_v2(&s[(bB * NC + n) * OUT_DIM + 2 * q], b0, b1);
    }
}

// final squash of g_s[2] -> output
__global__ void squash_out_kernel(float* out) {
    int idx = blockIdx.x * blockDim.x + threadIdx.x;
    if (idx >= BATCH * NC) return;
    float w[OUT_DIM];
    squash_row(&g_s[2][idx * OUT_DIM], 1.0f, w);
#pragma unroll
    for (int e = 0; e < OUT_DIM; e++) out[idx * OUT_DIM + e] = w[e];
}

extern "C" void kernel_launch(void* const* d_in, const int* in_sizes, int n_in,
                              void* d_out, int out_size) {
    const float* x = (const float*)d_in[0];   // [64, 2048, 8]
    const float* W = (const float*)d_in[1];   // [2048, 32, 8, 16]
    float* out = (float*)d_out;               // [64, 32, 16]

    transpose_W<<<IN_CAPS, 256>>>((const float4*)W);   // also zeroes g_s

    dim3 gridA(NIB_A, NBT);                   // 64 x 8  = 512 CTAs
    dim3 gridB(NIB_B, NBT);                   // 128 x 8 = 1024 CTAs
    dim3 sgrid((BATCH * NC + 255) / 256);

    passA_kernel<<<gridA, 128>>>(x);
    route_kernel<1><<<gridB, 128>>>();        // logit = u.v0      (squash inline)
    route_kernel<2><<<gridB, 128>>>();        // logit = u.(v0+v1) (squash inline)
    squash_out_kernel<<<sgrid, 256>>>(out);
}